// round 2
// baseline (speedup 1.0000x reference)
#include <cuda_runtime.h>
#include <math.h>

#define NN 50000
#define D 128
#define LAY 3
#define RK 16
#define NE 1600000

// ---------------- static device scratch ----------------
static __device__ int d_cnt[NN];
static __device__ int d_rowptr[NN + 1];
static __device__ int d_cursor[NN];
static __device__ int d_scol[NE];
static __device__ __align__(16) float d_sval[NE];
static __device__ __align__(16) float d_h[NN * D];
static __device__ __align__(16) float d_agg[NN * D];
static __device__ __align__(16) float d_zsum[D];
static __device__ __align__(16) float d_hz[D];
static __device__ __align__(16) float d_wcol[RK * D];

// ---------------- CSR build ----------------
__global__ void k_zero() {
    int i = blockIdx.x * blockDim.x + threadIdx.x;
    if (i < NN) d_cnt[i] = 0;
    if (i < D) d_zsum[i] = 0.f;
}

__global__ void k_hist(const int* __restrict__ rows) {
    int e = blockIdx.x * blockDim.x + threadIdx.x;
    if (e < NE) atomicAdd(&d_cnt[rows[e]], 1);
}

// single-block scan, warp-shuffle based (2 barriers per 1024-chunk)
__global__ void k_scan() {
    __shared__ int wsum[32];
    int t = threadIdx.x, lane = t & 31, wid = t >> 5;
    int carry = 0;
    for (int base = 0; base < NN; base += 1024) {
        int i = base + t;
        int v = (i < NN) ? d_cnt[i] : 0;
        int x = v;
        #pragma unroll
        for (int off = 1; off < 32; off <<= 1) {
            int y = __shfl_up_sync(0xffffffffu, x, off);
            if (lane >= off) x += y;
        }
        if (lane == 31) wsum[wid] = x;
        __syncthreads();
        if (wid == 0) {
            int s = wsum[lane];
            #pragma unroll
            for (int off = 1; off < 32; off <<= 1) {
                int y = __shfl_up_sync(0xffffffffu, s, off);
                if (lane >= off) s += y;
            }
            wsum[lane] = s;
        }
        __syncthreads();
        int blockoff = (wid > 0) ? wsum[wid - 1] : 0;
        int excl = x + blockoff - v;
        if (i < NN) { d_rowptr[i] = carry + excl; d_cursor[i] = carry + excl; }
        int tot = wsum[31];
        __syncthreads();
        carry += tot;
    }
    if (t == 0) d_rowptr[NN] = carry;
}

__global__ void k_scatter(const int* __restrict__ rows, const int* __restrict__ cols,
                          const float* __restrict__ vals) {
    int e = blockIdx.x * blockDim.x + threadIdx.x;
    if (e < NE) {
        int p = atomicAdd(&d_cursor[rows[e]], 1);
        d_scol[p] = cols[e];
        d_sval[p] = vals[e];
    }
}

// ---------------- column sums of node_feats into zsum ----------------
__global__ void k_colsum(const float* __restrict__ x) {
    int dcol = threadIdx.x;
    int r0 = blockIdx.x * 256;
    int r1 = min(r0 + 256, NN);
    float s = 0.f;
    for (int r = r0; r < r1; r++) s += x[(size_t)r * D + dcol];
    atomicAdd(&d_zsum[dcol], s);
}

// ---------------- SpMM: warp per row, 8-deep software pipeline (MLP=8) ----------------
__global__ void __launch_bounds__(256) k_spmm(const float* __restrict__ hin) {
    int w = (blockIdx.x * blockDim.x + threadIdx.x) >> 5;
    int lane = threadIdx.x & 31;
    if (w >= NN) return;
    int e0 = d_rowptr[w], e1 = d_rowptr[w + 1];
    float4 acc = make_float4(0.f, 0.f, 0.f, 0.f);
    for (int e = e0; e < e1; e += 32) {
        int idx = e + lane;
        int   myc = 0;
        float myv = 0.f;
        if (idx < e1) { myc = d_scol[idx]; myv = d_sval[idx]; }
        int nb = e1 - e; if (nb > 32) nb = 32;
        for (int jb = 0; jb < nb; jb += 8) {
            float4 hv[8];
            float  vv[8];
            #pragma unroll
            for (int u = 0; u < 8; u++) {
                int   c = __shfl_sync(0xffffffffu, myc, jb + u);
                vv[u]   = __shfl_sync(0xffffffffu, myv, jb + u);
                hv[u]   = *(const float4*)(hin + (size_t)c * D + lane * 4);
            }
            #pragma unroll
            for (int u = 0; u < 8; u++) {
                acc.x += vv[u] * hv[u].x;
                acc.y += vv[u] * hv[u].y;
                acc.z += vv[u] * hv[u].z;
                acc.w += vv[u] * hv[u].w;
            }
        }
    }
    *(float4*)(d_agg + (size_t)w * D + lane * 4) = acc;
}

// ---------------- GEMM: h = elu(agg @ W^T + b), epilogue accumulates column sums ----------------
#define GEMM_SMEM ((128 * 68 + 128 * 132 + 16 * 128) * 4)

__global__ void __launch_bounds__(256) k_gemm(const float* __restrict__ A,
                                              const float* __restrict__ W,
                                              const float* __restrict__ b) {
    extern __shared__ float sm[];
    float (*At)[68]  = (float (*)[68])sm;                  // [k][row]
    float (*Wt)[132] = (float (*)[132])(sm + 128 * 68);    // [k][n]
    float (*sp)[128] = (float (*)[128])(sm + 128 * 68 + 128 * 132);

    int tid = threadIdx.x;
    int rb = blockIdx.x * 64;

    #pragma unroll
    for (int t = 0; t < 8; t++) {
        int idx = tid + t * 256;
        int row = idx >> 5, kq = idx & 31;
        int ri = rb + row;
        float4 v = make_float4(0.f, 0.f, 0.f, 0.f);
        if (ri < NN) v = *(const float4*)(A + (size_t)ri * D + kq * 4);
        At[kq * 4 + 0][row] = v.x; At[kq * 4 + 1][row] = v.y;
        At[kq * 4 + 2][row] = v.z; At[kq * 4 + 3][row] = v.w;
    }
    #pragma unroll
    for (int t = 0; t < 16; t++) {
        int idx = tid + t * 256;
        int n = idx >> 5, kq = idx & 31;
        float4 v = *(const float4*)(W + n * D + kq * 4);
        Wt[kq * 4 + 0][n] = v.x; Wt[kq * 4 + 1][n] = v.y;
        Wt[kq * 4 + 2][n] = v.z; Wt[kq * 4 + 3][n] = v.w;
    }
    __syncthreads();

    int ty = tid >> 4, tx = tid & 15;
    int r0 = ty * 4, n0 = tx * 8;

    float4 acc[4][2];
    #pragma unroll
    for (int i = 0; i < 4; i++) { acc[i][0] = make_float4(0,0,0,0); acc[i][1] = make_float4(0,0,0,0); }

    #pragma unroll 4
    for (int k = 0; k < D; k++) {
        float4 a  = *(float4*)&At[k][r0];
        float4 b0 = *(float4*)&Wt[k][n0];
        float4 b1 = *(float4*)&Wt[k][n0 + 4];
        #pragma unroll
        for (int i = 0; i < 4; i++) {
            float ai = (i == 0) ? a.x : (i == 1) ? a.y : (i == 2) ? a.z : a.w;
            acc[i][0].x += ai * b0.x; acc[i][0].y += ai * b0.y;
            acc[i][0].z += ai * b0.z; acc[i][0].w += ai * b0.w;
            acc[i][1].x += ai * b1.x; acc[i][1].y += ai * b1.y;
            acc[i][1].z += ai * b1.z; acc[i][1].w += ai * b1.w;
        }
    }

    float4 bb0 = *(const float4*)(b + n0);
    float4 bb1 = *(const float4*)(b + n0 + 4);
    float csum[8] = {0,0,0,0,0,0,0,0};

    #pragma unroll
    for (int i = 0; i < 4; i++) {
        int ri = rb + r0 + i;
        if (ri < NN) {
            float o[8];
            float t0[8] = {acc[i][0].x + bb0.x, acc[i][0].y + bb0.y, acc[i][0].z + bb0.z, acc[i][0].w + bb0.w,
                           acc[i][1].x + bb1.x, acc[i][1].y + bb1.y, acc[i][1].z + bb1.z, acc[i][1].w + bb1.w};
            #pragma unroll
            for (int j = 0; j < 8; j++) {
                float tt = t0[j];
                o[j] = tt > 0.f ? tt : (__expf(tt) - 1.f);
                csum[j] += o[j];
            }
            *(float4*)(d_h + (size_t)ri * D + n0)     = make_float4(o[0], o[1], o[2], o[3]);
            *(float4*)(d_h + (size_t)ri * D + n0 + 4) = make_float4(o[4], o[5], o[6], o[7]);
        }
    }
    #pragma unroll
    for (int j = 0; j < 8; j++) sp[ty][n0 + j] = csum[j];
    __syncthreads();
    if (tid < D) {
        float tot = 0.f;
        #pragma unroll
        for (int q = 0; q < 16; q++) tot += sp[q][tid];
        atomicAdd(&d_zsum[tid], tot);
    }
}

// ---------------- z -> hz ----------------
__global__ void k_zhz(const float* __restrict__ fc1W, const float* __restrict__ fc1b) {
    __shared__ float zs[D];
    int dcol = threadIdx.x;
    zs[dcol] = d_zsum[dcol] * (1.0f / ((float)(LAY + 1) * (float)NN));
    __syncthreads();
    float s = fc1b[dcol];
    #pragma unroll 8
    for (int k = 0; k < D; k++) s += zs[k] * fc1W[dcol * D + k];
    d_hz[dcol] = s > 0.f ? s : 0.2f * s;
}

// ---------------- W_col ----------------
__global__ void k_wcolk(const float* __restrict__ Wc, const float* __restrict__ bc) {
    int gw = (blockIdx.x * blockDim.x + threadIdx.x) >> 5;
    int lane = threadIdx.x & 31;
    float4 hz4 = *(const float4*)(d_hz + lane * 4);
    for (int j = gw; j < RK * D; j += 512) {
        float4 w = *(const float4*)(Wc + (size_t)j * D + lane * 4);
        float p = hz4.x * w.x + hz4.y * w.y + hz4.z * w.z + hz4.w * w.w;
        #pragma unroll
        for (int o = 16; o > 0; o >>= 1) p += __shfl_xor_sync(0xffffffffu, p, o);
        if (lane == 0) d_wcol[j] = p + bc[j];
    }
}

// ---------------- fused final: W_row GEMV + W_u + update ----------------
__global__ void __launch_bounds__(256) k_final(const float* __restrict__ Wr,
                                               const float* __restrict__ br,
                                               const float* __restrict__ ini,
                                               float* __restrict__ out) {
    __shared__ float swc[RK][D];
    __shared__ float swr[8][RK];
    int tid = threadIdx.x;
    #pragma unroll
    for (int t = 0; t < 8; t++) {
        int idx = tid + t * 256;
        ((float*)swc)[idx] = d_wcol[idx];
    }
    int warp = tid >> 5, lane = tid & 31;
    float4 hz4 = *(const float4*)(d_hz + lane * 4);
    __syncthreads();

    int node = blockIdx.x * 8 + warp;
    const float* wbase = Wr + (size_t)node * RK * D;
    #pragma unroll
    for (int r = 0; r < RK; r++) {
        float4 w = *(const float4*)(wbase + (size_t)r * D + lane * 4);
        float p = hz4.x * w.x + hz4.y * w.y + hz4.z * w.z + hz4.w * w.w;
        #pragma unroll
        for (int o = 16; o > 0; o >>= 1) p += __shfl_xor_sync(0xffffffffu, p, o);
        if (lane == 0) swr[warp][r] = p + br[(size_t)node * RK + r];
    }
    __syncwarp();

    float4 wu = make_float4(0.f, 0.f, 0.f, 0.f);
    #pragma unroll
    for (int r = 0; r < RK; r++) {
        float wr_ = swr[warp][r];
        float4 wc = *(const float4*)&swc[r][lane * 4];
        wu.x += wr_ * wc.x; wu.y += wr_ * wc.y; wu.z += wr_ * wc.z; wu.w += wr_ * wc.w;
    }
    float4 iv = *(const float4*)(ini + (size_t)node * D + lane * 4);
    float4 ov;
    ov.x = iv.x + wu.x * iv.x;
    ov.y = iv.y + wu.y * iv.y;
    ov.z = iv.z + wu.z * iv.z;
    ov.w = iv.w + wu.w * iv.w;
    *(float4*)(out + (size_t)node * D + lane * 4) = ov;
}

// ---------------- launch ----------------
extern "C" void kernel_launch(void* const* d_in, const int* in_sizes, int n_in,
                              void* d_out, int out_size) {
    const int*   rows  = (const int*)d_in[0];
    const int*   cols  = (const int*)d_in[1];
    const float* vals  = (const float*)d_in[2];
    const float* feats = (const float*)d_in[3];
    const float* gW    = (const float*)d_in[4];
    const float* gb    = (const float*)d_in[5];
    const float* fc1W  = (const float*)d_in[6];
    const float* fc1b  = (const float*)d_in[7];
    const float* frW   = (const float*)d_in[8];
    const float* frb   = (const float*)d_in[9];
    const float* fcW   = (const float*)d_in[10];
    const float* fcb   = (const float*)d_in[11];
    const float* ini   = (const float*)d_in[12];
    float* out = (float*)d_out;

    cudaFuncSetAttribute(k_gemm, cudaFuncAttributeMaxDynamicSharedMemorySize, GEMM_SMEM);

    k_zero<<<196, 256>>>();
    k_hist<<<6250, 256>>>(rows);
    k_scan<<<1, 1024>>>();
    k_scatter<<<6250, 256>>>(rows, cols, vals);
    k_colsum<<<196, 128>>>(feats);

    for (int l = 0; l < LAY; l++) {
        const float* hin = (l == 0) ? feats : d_h;
        k_spmm<<<6250, 256>>>(hin);
        k_gemm<<<782, 256, GEMM_SMEM>>>(d_agg, gW + (size_t)l * D * D, gb + (size_t)l * D);
    }

    k_zhz<<<1, 128>>>(fc1W, fc1b);
    k_wcolk<<<64, 256>>>(fcW, fcb);
    k_final<<<6250, 256>>>(frW, frb, ini, out);
}

// round 5
// speedup vs baseline: 16.0400x; 16.0400x over previous
#include <cuda_runtime.h>

#define NN 50000
#define D 128
#define LAY 3
#define RK 16
#define NE 1600000
#define NB 148
#define NTHREADS (NB * 1024)
#define NWARPS (NB * 32)
#define CHUNK 338              // 148*338 = 50024 >= 50000
#define NTILES ((NN + 127) / 128)   // 391
#define PAD 132                // float4-aligned row pitch
#define SMEM_BYTES (2 * 128 * PAD * 4)

// ---------------- static device scratch ----------------
static __device__ int d_cnt[NN];
static __device__ int d_rowptr[NN + 1];
static __device__ int d_cursor[NN];
static __device__ int d_btot[NB];
static __device__ int d_boff[NB];
static __device__ int d_scol[NE];
static __device__ __align__(16) float d_sval[NE];
static __device__ __align__(16) float d_h[NN * D];
static __device__ __align__(16) float d_agg[NN * D];
static __device__ __align__(16) float d_zsum[D];

static __device__ unsigned bar_count = 0;
static __device__ volatile unsigned bar_gen = 0;

__device__ __forceinline__ void gridbar() {
    __syncthreads();
    __threadfence();                      // release (gpu scope)
    if (threadIdx.x == 0) {
        unsigned g = bar_gen;
        if (atomicAdd(&bar_count, 1u) == NB - 1) {
            bar_count = 0;
            __threadfence();
            bar_gen = g + 1;
        } else {
            while (bar_gen == g) { __nanosleep(64); }
        }
    }
    __syncthreads();
    __threadfence();                      // acquire
}

__device__ __forceinline__ float eluf(float t) {
    return t > 0.f ? t : (__expf(t) - 1.f);
}

__global__ void __launch_bounds__(1024, 1)
k_all(const int* __restrict__ rows, const int* __restrict__ cols,
      const float* __restrict__ vals, const float* __restrict__ feats,
      const float* __restrict__ gW, const float* __restrict__ gb,
      const float* __restrict__ fc1W, const float* __restrict__ fc1b,
      const float* __restrict__ frW, const float* __restrict__ frb,
      const float* __restrict__ fcW, const float* __restrict__ fcb,
      const float* __restrict__ ini, float* __restrict__ out)
{
    extern __shared__ float sm[];
    const int tid  = threadIdx.x;
    const int bid  = blockIdx.x;
    const int gtid = bid * 1024 + tid;
    const int lane = tid & 31;
    const int wid  = tid >> 5;
    const int gwarp = bid * 32 + wid;

    // ---------- phase 0: zero counters ----------
    for (int i = gtid; i < NN; i += NTHREADS) d_cnt[i] = 0;
    if (gtid < D) d_zsum[gtid] = 0.f;
    gridbar();

    // ---------- phase 1: histogram + column sums of feats ----------
    for (int e = gtid; e < NE; e += NTHREADS) atomicAdd(&d_cnt[rows[e]], 1);
    {
        float4 cacc = make_float4(0.f, 0.f, 0.f, 0.f);
        for (int r = gwarp; r < NN; r += NWARPS) {
            float4 v = *(const float4*)(feats + (size_t)r * D + lane * 4);
            cacc.x += v.x; cacc.y += v.y; cacc.z += v.z; cacc.w += v.w;
        }
        float* scol = sm;
        if (tid < D) scol[tid] = 0.f;
        __syncthreads();
        atomicAdd(&scol[lane * 4 + 0], cacc.x);
        atomicAdd(&scol[lane * 4 + 1], cacc.y);
        atomicAdd(&scol[lane * 4 + 2], cacc.z);
        atomicAdd(&scol[lane * 4 + 3], cacc.w);
        __syncthreads();
        if (tid < D) atomicAdd(&d_zsum[tid], scol[tid]);
    }
    gridbar();

    // ---------- scan A: per-block exclusive scan of its chunk ----------
    {
        int* s = (int*)sm;
        int base = bid * CHUNK;
        int i = base + tid;
        int v = (tid < CHUNK && i < NN) ? d_cnt[i] : 0;
        s[tid] = v;
        __syncthreads();
        #pragma unroll
        for (int off = 1; off < 1024; off <<= 1) {
            int a = (tid >= off) ? s[tid - off] : 0;
            __syncthreads();
            s[tid] += a;
            __syncthreads();
        }
        if (tid < CHUNK && i < NN) d_rowptr[i] = s[tid] - v;
        if (tid == 0) d_btot[bid] = s[1023];
    }
    gridbar();

    // ---------- scan B: block 0 scans block totals ----------
    if (bid == 0) {
        int* s = (int*)sm;
        int v = (tid < NB) ? d_btot[tid] : 0;
        s[tid] = v;
        __syncthreads();
        #pragma unroll
        for (int off = 1; off < 1024; off <<= 1) {
            int a = (tid >= off) ? s[tid - off] : 0;
            __syncthreads();
            s[tid] += a;
            __syncthreads();
        }
        if (tid < NB) d_boff[tid] = s[tid] - v;
        if (tid == 0) d_rowptr[NN] = s[1023];
    }
    gridbar();

    // ---------- scan C: add offsets, init cursors ----------
    {
        int off = d_boff[bid];
        int base = bid * CHUNK;
        int i = base + tid;
        if (tid < CHUNK && i < NN) {
            int val = d_rowptr[i] + off;
            d_rowptr[i] = val;
            d_cursor[i] = val;
        }
    }
    gridbar();

    // ---------- scatter into CSR ----------
    for (int e = gtid; e < NE; e += NTHREADS) {
        int p = atomicAdd(&d_cursor[rows[e]], 1);
        d_scol[p] = cols[e];
        d_sval[p] = vals[e];
    }
    gridbar();

    // ---------- GNN layers ----------
    for (int l = 0; l < LAY; l++) {
        const float* hin = (l == 0) ? feats : d_h;

        // SpMM: warp per row, 8-deep pipeline
        for (int row = gwarp; row < NN; row += NWARPS) {
            int e0 = d_rowptr[row], e1 = d_rowptr[row + 1];
            float4 acc = make_float4(0.f, 0.f, 0.f, 0.f);
            for (int e = e0; e < e1; e += 32) {
                int idx = e + lane;
                int myc = 0; float myv = 0.f;
                if (idx < e1) { myc = d_scol[idx]; myv = d_sval[idx]; }
                int nb = e1 - e; if (nb > 32) nb = 32;
                for (int jb = 0; jb < nb; jb += 8) {
                    float4 hv[8]; float vv[8];
                    #pragma unroll
                    for (int u = 0; u < 8; u++) {
                        int c  = __shfl_sync(0xffffffffu, myc, jb + u);
                        vv[u]  = __shfl_sync(0xffffffffu, myv, jb + u);
                        hv[u]  = *(const float4*)(hin + (size_t)c * D + lane * 4);
                    }
                    #pragma unroll
                    for (int u = 0; u < 8; u++) {
                        acc.x += vv[u] * hv[u].x; acc.y += vv[u] * hv[u].y;
                        acc.z += vv[u] * hv[u].z; acc.w += vv[u] * hv[u].w;
                    }
                }
            }
            *(float4*)(d_agg + (size_t)row * D + lane * 4) = acc;
        }
        gridbar();

        // GEMM: h = elu(agg @ W^T + b), tiles of 128x128
        const float* W = gW + (size_t)l * D * D;
        float colacc = 0.f;
        for (int tile = bid; tile < NTILES; tile += NB) {
            int rb = tile * 128;
            float (*At)[PAD] = (float (*)[PAD])sm;
            float (*Wt)[PAD] = (float (*)[PAD])(sm + 128 * PAD);
            #pragma unroll
            for (int t = 0; t < 4; t++) {
                int idx = tid + t * 1024;
                int row = idx >> 5, kq = idx & 31;
                int ri = rb + row;
                float4 v = make_float4(0.f, 0.f, 0.f, 0.f);
                if (ri < NN) v = *(const float4*)(d_agg + (size_t)ri * D + kq * 4);
                At[kq * 4 + 0][row] = v.x; At[kq * 4 + 1][row] = v.y;
                At[kq * 4 + 2][row] = v.z; At[kq * 4 + 3][row] = v.w;
            }
            #pragma unroll
            for (int t = 0; t < 4; t++) {
                int idx = tid + t * 1024;
                int n = idx >> 5, kq = idx & 31;
                float4 v = *(const float4*)(W + (size_t)n * D + kq * 4);
                Wt[kq * 4 + 0][n] = v.x; Wt[kq * 4 + 1][n] = v.y;
                Wt[kq * 4 + 2][n] = v.z; Wt[kq * 4 + 3][n] = v.w;
            }
            __syncthreads();

            int ty = wid, tx = lane;
            int r0 = ty * 4, n0 = tx * 4;
            float4 acc0 = make_float4(0,0,0,0), acc1 = make_float4(0,0,0,0);
            float4 acc2 = make_float4(0,0,0,0), acc3 = make_float4(0,0,0,0);
            #pragma unroll 4
            for (int k = 0; k < D; k++) {
                float4 a  = *(float4*)&At[k][r0];
                float4 bb = *(float4*)&Wt[k][n0];
                acc0.x += a.x * bb.x; acc0.y += a.x * bb.y; acc0.z += a.x * bb.z; acc0.w += a.x * bb.w;
                acc1.x += a.y * bb.x; acc1.y += a.y * bb.y; acc1.z += a.y * bb.z; acc1.w += a.y * bb.w;
                acc2.x += a.z * bb.x; acc2.y += a.z * bb.y; acc2.z += a.z * bb.z; acc2.w += a.z * bb.w;
                acc3.x += a.w * bb.x; acc3.y += a.w * bb.y; acc3.z += a.w * bb.z; acc3.w += a.w * bb.w;
            }
            __syncthreads();

            float4 bv = *(const float4*)(gb + l * D + n0);
            float4 cs = make_float4(0.f, 0.f, 0.f, 0.f);
            #pragma unroll
            for (int i = 0; i < 4; i++) {
                int ri = rb + r0 + i;
                float4 av = (i == 0) ? acc0 : (i == 1) ? acc1 : (i == 2) ? acc2 : acc3;
                if (ri < NN) {
                    float4 o;
                    o.x = eluf(av.x + bv.x); o.y = eluf(av.y + bv.y);
                    o.z = eluf(av.z + bv.z); o.w = eluf(av.w + bv.w);
                    *(float4*)(d_h + (size_t)ri * D + n0) = o;
                    cs.x += o.x; cs.y += o.y; cs.z += o.z; cs.w += o.w;
                }
            }
            float (*sp)[128] = (float (*)[128])sm;
            sp[ty][n0 + 0] = cs.x; sp[ty][n0 + 1] = cs.y;
            sp[ty][n0 + 2] = cs.z; sp[ty][n0 + 3] = cs.w;
            __syncthreads();
            if (tid < D) {
                float s = 0.f;
                #pragma unroll
                for (int q = 0; q < 32; q++) s += sp[q][tid];
                colacc += s;
            }
            __syncthreads();
        }
        if (tid < D) atomicAdd(&d_zsum[tid], colacc);
        gridbar();
    }

    // ---------- tail: z -> hz -> wcol (block-redundant), then final ----------
    float* s_hz   = sm;          // 128 floats
    float* s_wcol = sm + 128;    // 2048 floats
    {
        const float inv = 1.0f / ((float)(LAY + 1) * (float)NN);
        float4 z4 = *(const float4*)(d_zsum + lane * 4);
        z4.x *= inv; z4.y *= inv; z4.z *= inv; z4.w *= inv;
        for (int o = wid; o < D; o += 32) {
            float4 w = *(const float4*)(fc1W + (size_t)o * D + lane * 4);
            float p = z4.x * w.x + z4.y * w.y + z4.z * w.z + z4.w * w.w;
            #pragma unroll
            for (int off = 16; off > 0; off >>= 1) p += __shfl_xor_sync(0xffffffffu, p, off);
            if (lane == 0) {
                float s = p + fc1b[o];
                s_hz[o] = s > 0.f ? s : 0.2f * s;
            }
        }
        __syncthreads();
    }
    {
        float4 hz4 = *(const float4*)(s_hz + lane * 4);
        for (int j = wid; j < RK * D; j += 32) {
            float4 w = *(const float4*)(fcW + (size_t)j * D + lane * 4);
            float p = hz4.x * w.x + hz4.y * w.y + hz4.z * w.z + hz4.w * w.w;
            #pragma unroll
            for (int off = 16; off > 0; off >>= 1) p += __shfl_xor_sync(0xffffffffu, p, off);
            if (lane == 0) s_wcol[j] = p + fcb[j];
        }
        __syncthreads();
    }
    {
        float4 hz4 = *(const float4*)(s_hz + lane * 4);
        for (int node = gwarp; node < NN; node += NWARPS) {
            const float* wb = frW + (size_t)node * RK * D;
            float4 wu = make_float4(0.f, 0.f, 0.f, 0.f);
            #pragma unroll
            for (int r = 0; r < RK; r++) {
                float4 w = *(const float4*)(wb + r * D + lane * 4);
                float p = hz4.x * w.x + hz4.y * w.y + hz4.z * w.z + hz4.w * w.w;
                #pragma unroll
                for (int off = 16; off > 0; off >>= 1) p += __shfl_xor_sync(0xffffffffu, p, off);
                float wr = p + frb[(size_t)node * RK + r];
                float4 wc = *(const float4*)(s_wcol + r * D + lane * 4);
                wu.x += wr * wc.x; wu.y += wr * wc.y;
                wu.z += wr * wc.z; wu.w += wr * wc.w;
            }
            float4 iv = *(const float4*)(ini + (size_t)node * D + lane * 4);
            float4 ov;
            ov.x = iv.x + wu.x * iv.x; ov.y = iv.y + wu.y * iv.y;
            ov.z = iv.z + wu.z * iv.z; ov.w = iv.w + wu.w * iv.w;
            *(float4*)(out + (size_t)node * D + lane * 4) = ov;
        }
    }
}

// ---------------- launch ----------------
extern "C" void kernel_launch(void* const* d_in, const int* in_sizes, int n_in,
                              void* d_out, int out_size) {
    const int*   rows  = (const int*)d_in[0];
    const int*   cols  = (const int*)d_in[1];
    const float* vals  = (const float*)d_in[2];
    const float* feats = (const float*)d_in[3];
    const float* gW    = (const float*)d_in[4];
    const float* gb    = (const float*)d_in[5];
    const float* fc1W  = (const float*)d_in[6];
    const float* fc1b  = (const float*)d_in[7];
    const float* frW   = (const float*)d_in[8];
    const float* frb   = (const float*)d_in[9];
    const float* fcW   = (const float*)d_in[10];
    const float* fcb   = (const float*)d_in[11];
    const float* ini   = (const float*)d_in[12];
    float* out = (float*)d_out;

    cudaFuncSetAttribute(k_all, cudaFuncAttributeMaxDynamicSharedMemorySize, SMEM_BYTES);
    k_all<<<NB, 1024, SMEM_BYTES>>>(rows, cols, vals, feats, gW, gb,
                                    fc1W, fc1b, frW, frb, fcW, fcb, ini, out);
}

// round 6
// speedup vs baseline: 17.6631x; 1.1012x over previous
#include <cuda_runtime.h>
#include <cuda_bf16.h>

#define NN 50000
#define D 128
#define LAY 3
#define RK 16
#define NE 1600000
#define NB 148
#define NTHREADS (NB * 1024)
#define NWARPS (NB * 32)
#define CHUNK 338              // 148*338 = 50024 >= 50000
#define NTILES ((NN + 127) / 128)   // 391
#define PAD 132                // float4-aligned row pitch
#define SMEM_BYTES (2 * 128 * PAD * 4)

// ---------------- static device scratch ----------------
static __device__ int d_cnt[NN];
static __device__ int d_rowptr[NN + 1];
static __device__ int d_cursor[NN];
static __device__ int d_btot[NB];
static __device__ int d_boff[NB];
static __device__ int d_scol[NE];
static __device__ __align__(16) float d_sval[NE];
static __device__ __align__(16) __nv_bfloat16 d_hb[NN * D];   // h in bf16 (gather source)
static __device__ __align__(16) float d_agg[NN * D];
static __device__ __align__(16) float d_zsum[D];

static __device__ unsigned bar_count = 0;
static __device__ volatile unsigned bar_gen = 0;

__device__ __forceinline__ void gridbar() {
    __syncthreads();
    __threadfence();                      // release (gpu scope)
    if (threadIdx.x == 0) {
        unsigned g = bar_gen;
        if (atomicAdd(&bar_count, 1u) == NB - 1) {
            bar_count = 0;
            __threadfence();
            bar_gen = g + 1;
        } else {
            while (bar_gen == g) { __nanosleep(64); }
        }
    }
    __syncthreads();
    __threadfence();                      // acquire
}

__device__ __forceinline__ float eluf(float t) {
    return t > 0.f ? t : (__expf(t) - 1.f);
}

__global__ void __launch_bounds__(1024, 1)
k_all(const int* __restrict__ rows, const int* __restrict__ cols,
      const float* __restrict__ vals, const float* __restrict__ feats,
      const float* __restrict__ gW, const float* __restrict__ gb,
      const float* __restrict__ fc1W, const float* __restrict__ fc1b,
      const float* __restrict__ frW, const float* __restrict__ frb,
      const float* __restrict__ fcW, const float* __restrict__ fcb,
      const float* __restrict__ ini, float* __restrict__ out)
{
    extern __shared__ float sm[];
    const int tid  = threadIdx.x;
    const int bid  = blockIdx.x;
    const int gtid = bid * 1024 + tid;
    const int lane = tid & 31;
    const int wid  = tid >> 5;
    const int gwarp = bid * 32 + wid;

    // ---------- phase 0: zero counters ----------
    for (int i = gtid; i < NN; i += NTHREADS) d_cnt[i] = 0;
    if (gtid < D) d_zsum[gtid] = 0.f;
    gridbar();

    // ---------- phase 1: histogram + column sums + bf16 conversion of feats ----------
    for (int e = gtid; e < NE; e += NTHREADS) atomicAdd(&d_cnt[rows[e]], 1);
    {
        float4 cacc = make_float4(0.f, 0.f, 0.f, 0.f);
        for (int r = gwarp; r < NN; r += NWARPS) {
            float4 v = *(const float4*)(feats + (size_t)r * D + lane * 4);
            cacc.x += v.x; cacc.y += v.y; cacc.z += v.z; cacc.w += v.w;
            // convert this row's slice to bf16 for layer-0 SpMM gathers
            __nv_bfloat162* dst = (__nv_bfloat162*)(d_hb + (size_t)r * D + lane * 4);
            dst[0] = __floats2bfloat162_rn(v.x, v.y);
            dst[1] = __floats2bfloat162_rn(v.z, v.w);
        }
        float* scol = sm;
        if (tid < D) scol[tid] = 0.f;
        __syncthreads();
        atomicAdd(&scol[lane * 4 + 0], cacc.x);
        atomicAdd(&scol[lane * 4 + 1], cacc.y);
        atomicAdd(&scol[lane * 4 + 2], cacc.z);
        atomicAdd(&scol[lane * 4 + 3], cacc.w);
        __syncthreads();
        if (tid < D) atomicAdd(&d_zsum[tid], scol[tid]);
    }
    gridbar();

    // ---------- scan A: per-block exclusive scan of its chunk ----------
    {
        int* s = (int*)sm;
        int base = bid * CHUNK;
        int i = base + tid;
        int v = (tid < CHUNK && i < NN) ? d_cnt[i] : 0;
        s[tid] = v;
        __syncthreads();
        #pragma unroll
        for (int off = 1; off < 1024; off <<= 1) {
            int a = (tid >= off) ? s[tid - off] : 0;
            __syncthreads();
            s[tid] += a;
            __syncthreads();
        }
        if (tid < CHUNK && i < NN) d_rowptr[i] = s[tid] - v;
        if (tid == 0) d_btot[bid] = s[1023];
    }
    gridbar();

    // ---------- scan B: block 0 scans block totals ----------
    if (bid == 0) {
        int* s = (int*)sm;
        int v = (tid < NB) ? d_btot[tid] : 0;
        s[tid] = v;
        __syncthreads();
        #pragma unroll
        for (int off = 1; off < 1024; off <<= 1) {
            int a = (tid >= off) ? s[tid - off] : 0;
            __syncthreads();
            s[tid] += a;
            __syncthreads();
        }
        if (tid < NB) d_boff[tid] = s[tid] - v;
        if (tid == 0) d_rowptr[NN] = s[1023];
    }
    gridbar();

    // ---------- scan C: add offsets, init cursors ----------
    {
        int off = d_boff[bid];
        int base = bid * CHUNK;
        int i = base + tid;
        if (tid < CHUNK && i < NN) {
            int val = d_rowptr[i] + off;
            d_rowptr[i] = val;
            d_cursor[i] = val;
        }
    }
    gridbar();

    // ---------- scatter into CSR ----------
    for (int e = gtid; e < NE; e += NTHREADS) {
        int p = atomicAdd(&d_cursor[rows[e]], 1);
        d_scol[p] = cols[e];
        d_sval[p] = vals[e];
    }
    gridbar();

    // ---------- GNN layers ----------
    for (int l = 0; l < LAY; l++) {
        // SpMM: warp per row, 8-deep pipeline, bf16 gathers (8B per lane per edge)
        for (int row = gwarp; row < NN; row += NWARPS) {
            int e0 = d_rowptr[row], e1 = d_rowptr[row + 1];
            float4 acc = make_float4(0.f, 0.f, 0.f, 0.f);
            for (int e = e0; e < e1; e += 32) {
                int idx = e + lane;
                int myc = 0; float myv = 0.f;
                if (idx < e1) { myc = d_scol[idx]; myv = d_sval[idx]; }
                int nb = e1 - e; if (nb > 32) nb = 32;
                for (int jb = 0; jb < nb; jb += 8) {
                    uint2 hv[8]; float vv[8];
                    #pragma unroll
                    for (int u = 0; u < 8; u++) {
                        int c  = __shfl_sync(0xffffffffu, myc, jb + u);
                        vv[u]  = __shfl_sync(0xffffffffu, myv, jb + u);
                        hv[u]  = *(const uint2*)(d_hb + (size_t)c * D + lane * 4);
                    }
                    #pragma unroll
                    for (int u = 0; u < 8; u++) {
                        float2 f0 = __bfloat1622float2(*(const __nv_bfloat162*)&hv[u].x);
                        float2 f1 = __bfloat1622float2(*(const __nv_bfloat162*)&hv[u].y);
                        acc.x += vv[u] * f0.x; acc.y += vv[u] * f0.y;
                        acc.z += vv[u] * f1.x; acc.w += vv[u] * f1.y;
                    }
                }
            }
            *(float4*)(d_agg + (size_t)row * D + lane * 4) = acc;
        }
        gridbar();

        // GEMM: h = elu(agg @ W^T + b) -> bf16, epilogue accumulates column sums
        const float* W = gW + (size_t)l * D * D;
        float colacc = 0.f;
        for (int tile = bid; tile < NTILES; tile += NB) {
            int rb = tile * 128;
            float (*At)[PAD] = (float (*)[PAD])sm;
            float (*Wt)[PAD] = (float (*)[PAD])(sm + 128 * PAD);
            #pragma unroll
            for (int t = 0; t < 4; t++) {
                int idx = tid + t * 1024;
                int row = idx >> 5, kq = idx & 31;
                int ri = rb + row;
                float4 v = make_float4(0.f, 0.f, 0.f, 0.f);
                if (ri < NN) v = *(const float4*)(d_agg + (size_t)ri * D + kq * 4);
                At[kq * 4 + 0][row] = v.x; At[kq * 4 + 1][row] = v.y;
                At[kq * 4 + 2][row] = v.z; At[kq * 4 + 3][row] = v.w;
            }
            #pragma unroll
            for (int t = 0; t < 4; t++) {
                int idx = tid + t * 1024;
                int n = idx >> 5, kq = idx & 31;
                float4 v = *(const float4*)(W + (size_t)n * D + kq * 4);
                Wt[kq * 4 + 0][n] = v.x; Wt[kq * 4 + 1][n] = v.y;
                Wt[kq * 4 + 2][n] = v.z; Wt[kq * 4 + 3][n] = v.w;
            }
            __syncthreads();

            int ty = wid, tx = lane;
            int r0 = ty * 4, n0 = tx * 4;
            float4 acc0 = make_float4(0,0,0,0), acc1 = make_float4(0,0,0,0);
            float4 acc2 = make_float4(0,0,0,0), acc3 = make_float4(0,0,0,0);
            #pragma unroll 4
            for (int k = 0; k < D; k++) {
                float4 a  = *(float4*)&At[k][r0];
                float4 bb = *(float4*)&Wt[k][n0];
                acc0.x += a.x * bb.x; acc0.y += a.x * bb.y; acc0.z += a.x * bb.z; acc0.w += a.x * bb.w;
                acc1.x += a.y * bb.x; acc1.y += a.y * bb.y; acc1.z += a.y * bb.z; acc1.w += a.y * bb.w;
                acc2.x += a.z * bb.x; acc2.y += a.z * bb.y; acc2.z += a.z * bb.z; acc2.w += a.z * bb.w;
                acc3.x += a.w * bb.x; acc3.y += a.w * bb.y; acc3.z += a.w * bb.z; acc3.w += a.w * bb.w;
            }
            __syncthreads();

            float4 bv = *(const float4*)(gb + l * D + n0);
            float4 cs = make_float4(0.f, 0.f, 0.f, 0.f);
            #pragma unroll
            for (int i = 0; i < 4; i++) {
                int ri = rb + r0 + i;
                float4 av = (i == 0) ? acc0 : (i == 1) ? acc1 : (i == 2) ? acc2 : acc3;
                if (ri < NN) {
                    float4 o;
                    o.x = eluf(av.x + bv.x); o.y = eluf(av.y + bv.y);
                    o.z = eluf(av.z + bv.z); o.w = eluf(av.w + bv.w);
                    __nv_bfloat162* dst = (__nv_bfloat162*)(d_hb + (size_t)ri * D + n0);
                    dst[0] = __floats2bfloat162_rn(o.x, o.y);
                    dst[1] = __floats2bfloat162_rn(o.z, o.w);
                    cs.x += o.x; cs.y += o.y; cs.z += o.z; cs.w += o.w;
                }
            }
            float (*sp)[128] = (float (*)[128])sm;
            sp[ty][n0 + 0] = cs.x; sp[ty][n0 + 1] = cs.y;
            sp[ty][n0 + 2] = cs.z; sp[ty][n0 + 3] = cs.w;
            __syncthreads();
            if (tid < D) {
                float s = 0.f;
                #pragma unroll
                for (int q = 0; q < 32; q++) s += sp[q][tid];
                colacc += s;
            }
            __syncthreads();
        }
        if (tid < D) atomicAdd(&d_zsum[tid], colacc);
        gridbar();
    }

    // ---------- tail: z -> hz -> wcol (block-redundant), then final ----------
    float* s_hz   = sm;          // 128 floats
    float* s_wcol = sm + 128;    // 2048 floats
    {
        const float inv = 1.0f / ((float)(LAY + 1) * (float)NN);
        float4 z4 = *(const float4*)(d_zsum + lane * 4);
        z4.x *= inv; z4.y *= inv; z4.z *= inv; z4.w *= inv;
        for (int o = wid; o < D; o += 32) {
            float4 w = *(const float4*)(fc1W + (size_t)o * D + lane * 4);
            float p = z4.x * w.x + z4.y * w.y + z4.z * w.z + z4.w * w.w;
            #pragma unroll
            for (int off = 16; off > 0; off >>= 1) p += __shfl_xor_sync(0xffffffffu, p, off);
            if (lane == 0) {
                float s = p + fc1b[o];
                s_hz[o] = s > 0.f ? s : 0.2f * s;
            }
        }
        __syncthreads();
    }
    {
        float4 hz4 = *(const float4*)(s_hz + lane * 4);
        for (int j = wid; j < RK * D; j += 32) {
            float4 w = *(const float4*)(fcW + (size_t)j * D + lane * 4);
            float p = hz4.x * w.x + hz4.y * w.y + hz4.z * w.z + hz4.w * w.w;
            #pragma unroll
            for (int off = 16; off > 0; off >>= 1) p += __shfl_xor_sync(0xffffffffu, p, off);
            if (lane == 0) s_wcol[j] = p + fcb[j];
        }
        __syncthreads();
    }
    {
        float4 hz4 = *(const float4*)(s_hz + lane * 4);
        for (int node = gwarp; node < NN; node += NWARPS) {
            const float* wb = frW + (size_t)node * RK * D;
            float4 wu = make_float4(0.f, 0.f, 0.f, 0.f);
            #pragma unroll
            for (int r = 0; r < RK; r++) {
                float4 w = *(const float4*)(wb + r * D + lane * 4);
                float p = hz4.x * w.x + hz4.y * w.y + hz4.z * w.z + hz4.w * w.w;
                #pragma unroll
                for (int off = 16; off > 0; off >>= 1) p += __shfl_xor_sync(0xffffffffu, p, off);
                float wr = p + frb[(size_t)node * RK + r];
                float4 wc = *(const float4*)(s_wcol + r * D + lane * 4);
                wu.x += wr * wc.x; wu.y += wr * wc.y;
                wu.z += wr * wc.z; wu.w += wr * wc.w;
            }
            float4 iv = *(const float4*)(ini + (size_t)node * D + lane * 4);
            float4 ov;
            ov.x = iv.x + wu.x * iv.x; ov.y = iv.y + wu.y * iv.y;
            ov.z = iv.z + wu.z * iv.z; ov.w = iv.w + wu.w * iv.w;
            *(float4*)(out + (size_t)node * D + lane * 4) = ov;
        }
    }
}

// ---------------- launch ----------------
extern "C" void kernel_launch(void* const* d_in, const int* in_sizes, int n_in,
                              void* d_out, int out_size) {
    const int*   rows  = (const int*)d_in[0];
    const int*   cols  = (const int*)d_in[1];
    const float* vals  = (const float*)d_in[2];
    const float* feats = (const float*)d_in[3];
    const float* gW    = (const float*)d_in[4];
    const float* gb    = (const float*)d_in[5];
    const float* fc1W  = (const float*)d_in[6];
    const float* fc1b  = (const float*)d_in[7];
    const float* frW   = (const float*)d_in[8];
    const float* frb   = (const float*)d_in[9];
    const float* fcW   = (const float*)d_in[10];
    const float* fcb   = (const float*)d_in[11];
    const float* ini   = (const float*)d_in[12];
    float* out = (float*)d_out;

    cudaFuncSetAttribute(k_all, cudaFuncAttributeMaxDynamicSharedMemorySize, SMEM_BYTES);
    k_all<<<NB, 1024, SMEM_BYTES>>>(rows, cols, vals, feats, gW, gb,
                                    fc1W, fc1b, frW, frb, fcW, fcb, ini, out);
}

// round 7
// speedup vs baseline: 25.3485x; 1.4351x over previous
#include <cuda_runtime.h>
#include <cuda_bf16.h>

#define NN 50000
#define D 128
#define LAY 3
#define RK 16
#define NE 1600000
#define NB 148
#define NTHREADS (NB * 1024)
#define NWARPS (NB * 32)
#define CHUNK 338                    // 148*338 = 50024 >= 50000
#define NTILES ((NN + 127) / 128)    // 391
#define SPITCH 136                   // bf16 smem row pitch (272B, 16B-aligned, swizzle-ish)
#define SA_BYTES (128 * SPITCH * 2)  // 34816
#define SMEM_BYTES (2 * SA_BYTES + 512)

// ---------------- static device scratch ----------------
static __device__ int d_cnt[NN];
static __device__ int d_rowptr[NN + 1];
static __device__ int d_cursor[NN];
static __device__ int d_btot[NB];
static __device__ int d_boff[NB];
static __device__ int d_scol[NE];
static __device__ __align__(16) float d_sval[NE];
static __device__ __align__(16) __nv_bfloat16 d_hb[NN * D];    // h (bf16, gather source)
static __device__ __align__(16) __nv_bfloat16 d_aggb[NN * D];  // agg (bf16, GEMM A)
static __device__ __align__(16) __nv_bfloat16 d_wb[D * D];     // W_l (bf16, GEMM B)
static __device__ __align__(16) float d_zsum[D];

static __device__ unsigned bar_count = 0;
static __device__ volatile unsigned bar_gen = 0;

__device__ __forceinline__ void gridbar() {
    __syncthreads();
    __threadfence();
    if (threadIdx.x == 0) {
        unsigned g = bar_gen;
        if (atomicAdd(&bar_count, 1u) == NB - 1) {
            bar_count = 0;
            __threadfence();
            bar_gen = g + 1;
        } else {
            while (bar_gen == g) { __nanosleep(64); }
        }
    }
    __syncthreads();
    __threadfence();
}

__device__ __forceinline__ float eluf(float t) {
    return t > 0.f ? t : (__expf(t) - 1.f);
}

__device__ __forceinline__ void ldm_x4(unsigned r[4], unsigned addr) {
    asm volatile("ldmatrix.sync.aligned.m8n8.x4.shared.b16 {%0,%1,%2,%3}, [%4];"
                 : "=r"(r[0]), "=r"(r[1]), "=r"(r[2]), "=r"(r[3]) : "r"(addr));
}

__device__ __forceinline__ void mma_bf16(float c[4], const unsigned a[4],
                                         unsigned b0, unsigned b1) {
    asm volatile("mma.sync.aligned.m16n8k16.row.col.f32.bf16.bf16.f32 "
                 "{%0,%1,%2,%3}, {%4,%5,%6,%7}, {%8,%9}, {%0,%1,%2,%3};"
                 : "+f"(c[0]), "+f"(c[1]), "+f"(c[2]), "+f"(c[3])
                 : "r"(a[0]), "r"(a[1]), "r"(a[2]), "r"(a[3]), "r"(b0), "r"(b1));
}

__global__ void __launch_bounds__(1024, 1)
k_all(const int* __restrict__ rows, const int* __restrict__ cols,
      const float* __restrict__ vals, const float* __restrict__ feats,
      const float* __restrict__ gW, const float* __restrict__ gb,
      const float* __restrict__ fc1W, const float* __restrict__ fc1b,
      const float* __restrict__ frW, const float* __restrict__ frb,
      const float* __restrict__ fcW, const float* __restrict__ fcb,
      const float* __restrict__ ini, float* __restrict__ out)
{
    extern __shared__ float sm[];
    __nv_bfloat16* sA = (__nv_bfloat16*)sm;
    __nv_bfloat16* sB = (__nv_bfloat16*)((char*)sm + SA_BYTES);
    float* scol = (float*)((char*)sm + 2 * SA_BYTES);

    const int tid  = threadIdx.x;
    const int bid  = blockIdx.x;
    const int gtid = bid * 1024 + tid;
    const int lane = tid & 31;
    const int wid  = tid >> 5;
    const int gwarp = bid * 32 + wid;

    // ---------- phase 0 ----------
    for (int i = gtid; i < NN; i += NTHREADS) d_cnt[i] = 0;
    if (gtid < D) d_zsum[gtid] = 0.f;
    gridbar();

    // ---------- phase 1: histogram + colsum + feats->bf16 ----------
    for (int e = gtid; e < NE; e += NTHREADS) atomicAdd(&d_cnt[rows[e]], 1);
    {
        float4 cacc = make_float4(0.f, 0.f, 0.f, 0.f);
        for (int r = gwarp; r < NN; r += NWARPS) {
            float4 v = *(const float4*)(feats + (size_t)r * D + lane * 4);
            cacc.x += v.x; cacc.y += v.y; cacc.z += v.z; cacc.w += v.w;
            __nv_bfloat162* dst = (__nv_bfloat162*)(d_hb + (size_t)r * D + lane * 4);
            dst[0] = __floats2bfloat162_rn(v.x, v.y);
            dst[1] = __floats2bfloat162_rn(v.z, v.w);
        }
        if (tid < D) sm[tid] = 0.f;
        __syncthreads();
        atomicAdd(&sm[lane * 4 + 0], cacc.x);
        atomicAdd(&sm[lane * 4 + 1], cacc.y);
        atomicAdd(&sm[lane * 4 + 2], cacc.z);
        atomicAdd(&sm[lane * 4 + 3], cacc.w);
        __syncthreads();
        if (tid < D) atomicAdd(&d_zsum[tid], sm[tid]);
    }
    gridbar();

    // ---------- scan A ----------
    {
        int* s = (int*)sm;
        int base = bid * CHUNK;
        int i = base + tid;
        int v = (tid < CHUNK && i < NN) ? d_cnt[i] : 0;
        s[tid] = v;
        __syncthreads();
        #pragma unroll
        for (int off = 1; off < 1024; off <<= 1) {
            int a = (tid >= off) ? s[tid - off] : 0;
            __syncthreads();
            s[tid] += a;
            __syncthreads();
        }
        if (tid < CHUNK && i < NN) d_rowptr[i] = s[tid] - v;
        if (tid == 0) d_btot[bid] = s[1023];
    }
    gridbar();

    // ---------- scan B ----------
    if (bid == 0) {
        int* s = (int*)sm;
        int v = (tid < NB) ? d_btot[tid] : 0;
        s[tid] = v;
        __syncthreads();
        #pragma unroll
        for (int off = 1; off < 1024; off <<= 1) {
            int a = (tid >= off) ? s[tid - off] : 0;
            __syncthreads();
            s[tid] += a;
            __syncthreads();
        }
        if (tid < NB) d_boff[tid] = s[tid] - v;
        if (tid == 0) d_rowptr[NN] = s[1023];
    }
    gridbar();

    // ---------- scan C ----------
    {
        int off = d_boff[bid];
        int i = bid * CHUNK + tid;
        if (tid < CHUNK && i < NN) {
            int val = d_rowptr[i] + off;
            d_rowptr[i] = val;
            d_cursor[i] = val;
        }
    }
    gridbar();

    // ---------- scatter ----------
    for (int e = gtid; e < NE; e += NTHREADS) {
        int p = atomicAdd(&d_cursor[rows[e]], 1);
        d_scol[p] = cols[e];
        d_sval[p] = vals[e];
    }
    gridbar();

    // ---------- GNN layers ----------
    for (int l = 0; l < LAY; l++) {
        // convert this layer's W to bf16 (alongside SpMM)
        if (gtid < D * D / 4) {
            float4 v = *(const float4*)(gW + (size_t)l * D * D + gtid * 4);
            __nv_bfloat162* dst = (__nv_bfloat162*)(d_wb + gtid * 4);
            dst[0] = __floats2bfloat162_rn(v.x, v.y);
            dst[1] = __floats2bfloat162_rn(v.z, v.w);
        }

        // SpMM: warp per row, 8-deep pipeline, bf16 gathers, bf16 agg output
        for (int row = gwarp; row < NN; row += NWARPS) {
            int e0 = d_rowptr[row], e1 = d_rowptr[row + 1];
            float4 acc = make_float4(0.f, 0.f, 0.f, 0.f);
            for (int e = e0; e < e1; e += 32) {
                int idx = e + lane;
                int myc = 0; float myv = 0.f;
                if (idx < e1) { myc = d_scol[idx]; myv = d_sval[idx]; }
                int nb = e1 - e; if (nb > 32) nb = 32;
                for (int jb = 0; jb < nb; jb += 8) {
                    uint2 hv[8]; float vv[8];
                    #pragma unroll
                    for (int u = 0; u < 8; u++) {
                        int c  = __shfl_sync(0xffffffffu, myc, jb + u);
                        vv[u]  = __shfl_sync(0xffffffffu, myv, jb + u);
                        hv[u]  = *(const uint2*)(d_hb + (size_t)c * D + lane * 4);
                    }
                    #pragma unroll
                    for (int u = 0; u < 8; u++) {
                        float2 f0 = __bfloat1622float2(*(const __nv_bfloat162*)&hv[u].x);
                        float2 f1 = __bfloat1622float2(*(const __nv_bfloat162*)&hv[u].y);
                        acc.x += vv[u] * f0.x; acc.y += vv[u] * f0.y;
                        acc.z += vv[u] * f1.x; acc.w += vv[u] * f1.y;
                    }
                }
            }
            __nv_bfloat162* dst = (__nv_bfloat162*)(d_aggb + (size_t)row * D + lane * 4);
            dst[0] = __floats2bfloat162_rn(acc.x, acc.y);
            dst[1] = __floats2bfloat162_rn(acc.z, acc.w);
        }
        gridbar();

        // GEMM (tensor cores): h = elu(agg @ W^T + b) -> bf16
        if (tid < D) scol[tid] = 0.f;
        __syncthreads();

        const unsigned sA_base = (unsigned)__cvta_generic_to_shared(sA);
        const unsigned sB_base = (unsigned)__cvta_generic_to_shared(sB);
        const int wm = wid >> 2, wn = wid & 3;

        for (int tile = bid; tile < NTILES; tile += NB) {
            int rb = tile * 128;
            // load A tile (bf16, guarded) and B tile (W bf16)
            #pragma unroll
            for (int t = 0; t < 2; t++) {
                int j = tid + t * 1024;                 // 2048 segs of 8 bf16
                int row = j >> 4, seg = j & 15;
                int ri = rb + row;
                uint4 v = make_uint4(0, 0, 0, 0);
                if (ri < NN) v = *(const uint4*)(d_aggb + (size_t)ri * D + seg * 8);
                *(uint4*)(sA + row * SPITCH + seg * 8) = v;
            }
            #pragma unroll
            for (int t = 0; t < 2; t++) {
                int j = tid + t * 1024;
                int row = j >> 4, seg = j & 15;
                uint4 v = *(const uint4*)(d_wb + row * D + seg * 8);
                *(uint4*)(sB + row * SPITCH + seg * 8) = v;
            }
            __syncthreads();

            float c[4][4];
            #pragma unroll
            for (int f = 0; f < 4; f++)
                #pragma unroll
                for (int q = 0; q < 4; q++) c[f][q] = 0.f;

            #pragma unroll
            for (int ks = 0; ks < 8; ks++) {
                int k0 = ks * 16;
                unsigned a[4];
                unsigned aaddr = sA_base +
                    ((wm * 16 + (lane & 15)) * SPITCH + k0 + (lane >> 4) * 8) * 2;
                ldm_x4(a, aaddr);
                #pragma unroll
                for (int half = 0; half < 2; half++) {
                    int nbase = wn * 32 + half * 16;
                    int grp = lane >> 3;
                    int nrow = nbase + ((grp & 2) << 2) + (lane & 7);
                    int koff = k0 + ((grp & 1) << 3);
                    unsigned b[4];
                    unsigned baddr = sB_base + (nrow * SPITCH + koff) * 2;
                    ldm_x4(b, baddr);
                    mma_bf16(c[half * 2 + 0], a, b[0], b[1]);
                    mma_bf16(c[half * 2 + 1], a, b[2], b[3]);
                }
            }
            __syncthreads();   // done reading sA/sB

            // epilogue: bias + ELU, bf16 store, column sums
            int r0g = rb + wm * 16 + (lane >> 2);
            int r1g = r0g + 8;
            bool v0 = r0g < NN, v1 = r1g < NN;
            #pragma unroll
            for (int f = 0; f < 4; f++) {
                int nb = wn * 32 + f * 8 + (lane & 3) * 2;
                float b0 = gb[l * D + nb], b1 = gb[l * D + nb + 1];
                float o0 = eluf(c[f][0] + b0), o1 = eluf(c[f][1] + b1);
                float o2 = eluf(c[f][2] + b0), o3 = eluf(c[f][3] + b1);
                if (v0) *(__nv_bfloat162*)(d_hb + (size_t)r0g * D + nb) =
                            __floats2bfloat162_rn(o0, o1);
                if (v1) *(__nv_bfloat162*)(d_hb + (size_t)r1g * D + nb) =
                            __floats2bfloat162_rn(o2, o3);
                float s0 = (v0 ? o0 : 0.f) + (v1 ? o2 : 0.f);
                float s1 = (v0 ? o1 : 0.f) + (v1 ? o3 : 0.f);
                #pragma unroll
                for (int off = 4; off < 32; off <<= 1) {
                    s0 += __shfl_xor_sync(0xffffffffu, s0, off);
                    s1 += __shfl_xor_sync(0xffffffffu, s1, off);
                }
                if (lane < 4) {
                    atomicAdd(&scol[nb], s0);
                    atomicAdd(&scol[nb + 1], s1);
                }
            }
            __syncthreads();
        }
        if (tid < D) atomicAdd(&d_zsum[tid], scol[tid]);
        gridbar();
    }

    // ---------- tail ----------
    float* s_hz   = sm;
    float* s_wcol = sm + 128;
    {
        const float inv = 1.0f / ((float)(LAY + 1) * (float)NN);
        float4 z4 = *(const float4*)(d_zsum + lane * 4);
        z4.x *= inv; z4.y *= inv; z4.z *= inv; z4.w *= inv;
        for (int o = wid; o < D; o += 32) {
            float4 w = *(const float4*)(fc1W + (size_t)o * D + lane * 4);
            float p = z4.x * w.x + z4.y * w.y + z4.z * w.z + z4.w * w.w;
            #pragma unroll
            for (int off = 16; off > 0; off >>= 1) p += __shfl_xor_sync(0xffffffffu, p, off);
            if (lane == 0) {
                float s = p + fc1b[o];
                s_hz[o] = s > 0.f ? s : 0.2f * s;
            }
        }
        __syncthreads();
    }
    {
        float4 hz4 = *(const float4*)(s_hz + lane * 4);
        for (int j = wid; j < RK * D; j += 32) {
            float4 w = *(const float4*)(fcW + (size_t)j * D + lane * 4);
            float p = hz4.x * w.x + hz4.y * w.y + hz4.z * w.z + hz4.w * w.w;
            #pragma unroll
            for (int off = 16; off > 0; off >>= 1) p += __shfl_xor_sync(0xffffffffu, p, off);
            if (lane == 0) s_wcol[j] = p + fcb[j];
        }
        __syncthreads();
    }
    {
        float4 hz4 = *(const float4*)(s_hz + lane * 4);
        for (int node = gwarp; node < NN; node += NWARPS) {
            const float* wb = frW + (size_t)node * RK * D;
            float4 wu = make_float4(0.f, 0.f, 0.f, 0.f);
            #pragma unroll
            for (int r = 0; r < RK; r++) {
                float4 w = *(const float4*)(wb + r * D + lane * 4);
                float p = hz4.x * w.x + hz4.y * w.y + hz4.z * w.z + hz4.w * w.w;
                #pragma unroll
                for (int off = 16; off > 0; off >>= 1) p += __shfl_xor_sync(0xffffffffu, p, off);
                float wr = p + frb[(size_t)node * RK + r];
                float4 wc = *(const float4*)(s_wcol + r * D + lane * 4);
                wu.x += wr * wc.x; wu.y += wr * wc.y;
                wu.z += wr * wc.z; wu.w += wr * wc.w;
            }
            float4 iv = *(const float4*)(ini + (size_t)node * D + lane * 4);
            float4 ov;
            ov.x = iv.x + wu.x * iv.x; ov.y = iv.y + wu.y * iv.y;
            ov.z = iv.z + wu.z * iv.z; ov.w = iv.w + wu.w * iv.w;
            *(float4*)(out + (size_t)node * D + lane * 4) = ov;
        }
    }
}

// ---------------- launch ----------------
extern "C" void kernel_launch(void* const* d_in, const int* in_sizes, int n_in,
                              void* d_out, int out_size) {
    const int*   rows  = (const int*)d_in[0];
    const int*   cols  = (const int*)d_in[1];
    const float* vals  = (const float*)d_in[2];
    const float* feats = (const float*)d_in[3];
    const float* gW    = (const float*)d_in[4];
    const float* gb    = (const float*)d_in[5];
    const float* fc1W  = (const float*)d_in[6];
    const float* fc1b  = (const float*)d_in[7];
    const float* frW   = (const float*)d_in[8];
    const float* frb   = (const float*)d_in[9];
    const float* fcW   = (const float*)d_in[10];
    const float* fcb   = (const float*)d_in[11];
    const float* ini   = (const float*)d_in[12];
    float* out = (float*)d_out;

    cudaFuncSetAttribute(k_all, cudaFuncAttributeMaxDynamicSharedMemorySize, SMEM_BYTES);
    k_all<<<NB, 1024, SMEM_BYTES>>>(rows, cols, vals, feats, gW, gb,
                                    fc1W, fc1b, frW, frb, fcW, fcb, ini, out);
}

// round 8
// speedup vs baseline: 27.1390x; 1.0706x over previous
#include <cuda_runtime.h>
#include <cuda_bf16.h>

#define NN 50000
#define D 128
#define LAY 3
#define RK 16
#define NE 1600000
#define NB 148
#define NTHREADS (NB * 1024)
#define NWARPS (NB * 32)
#define CHUNK 338                    // 148*338 = 50024 >= 50000
#define NTILES ((NN + 127) / 128)    // 391
#define SPITCH 136                   // bf16 smem row pitch
#define SA_BYTES (128 * SPITCH * 2)  // 34816
#define SMEM_BYTES (2 * SA_BYTES + 512)

// ---------------- static device scratch ----------------
static __device__ int d_cnt[NN];          // zero at entry (BSS / re-zeroed each run)
static __device__ int d_rowptr[NN + 1];
static __device__ int d_cursor[NN];
static __device__ int d_btot[NB];
static __device__ int d_boff[NB];
static __device__ __align__(16) uint2 d_edge[NE];             // {col, val bits}
static __device__ __align__(16) __nv_bfloat16 d_hb[NN * D];   // h (bf16)
static __device__ __align__(16) float d_zsum[D];

static __device__ unsigned bar_count = 0;
static __device__ volatile unsigned bar_gen = 0;

__device__ __forceinline__ void gridbar() {
    __syncthreads();
    __threadfence();
    if (threadIdx.x == 0) {
        unsigned g = bar_gen;
        if (atomicAdd(&bar_count, 1u) == NB - 1) {
            bar_count = 0;
            __threadfence();
            bar_gen = g + 1;
        } else {
            while (bar_gen == g) { __nanosleep(64); }
        }
    }
    __syncthreads();
    __threadfence();
}

__device__ __forceinline__ float eluf(float t) {
    return t > 0.f ? t : (__expf(t) - 1.f);
}

__device__ __forceinline__ void ldm_x4(unsigned r[4], unsigned addr) {
    asm volatile("ldmatrix.sync.aligned.m8n8.x4.shared.b16 {%0,%1,%2,%3}, [%4];"
                 : "=r"(r[0]), "=r"(r[1]), "=r"(r[2]), "=r"(r[3]) : "r"(addr));
}

__device__ __forceinline__ void mma_bf16(float c[4], const unsigned a[4],
                                         unsigned b0, unsigned b1) {
    asm volatile("mma.sync.aligned.m16n8k16.row.col.f32.bf16.bf16.f32 "
                 "{%0,%1,%2,%3}, {%4,%5,%6,%7}, {%8,%9}, {%0,%1,%2,%3};"
                 : "+f"(c[0]), "+f"(c[1]), "+f"(c[2]), "+f"(c[3])
                 : "r"(a[0]), "r"(a[1]), "r"(a[2]), "r"(a[3]), "r"(b0), "r"(b1));
}

__global__ void __launch_bounds__(1024, 1)
k_all(const int* __restrict__ rows, const int* __restrict__ cols,
      const float* __restrict__ vals, const float* __restrict__ feats,
      const float* __restrict__ gW, const float* __restrict__ gb,
      const float* __restrict__ fc1W, const float* __restrict__ fc1b,
      const float* __restrict__ frW, const float* __restrict__ frb,
      const float* __restrict__ fcW, const float* __restrict__ fcb,
      const float* __restrict__ ini, float* __restrict__ out)
{
    extern __shared__ float sm[];
    __nv_bfloat16* sA = (__nv_bfloat16*)sm;
    __nv_bfloat16* sB = (__nv_bfloat16*)((char*)sm + SA_BYTES);
    float* scol = (float*)((char*)sm + 2 * SA_BYTES);   // 128 floats

    const int tid  = threadIdx.x;
    const int bid  = blockIdx.x;
    const int gtid = bid * 1024 + tid;
    const int lane = tid & 31;
    const int wid  = tid >> 5;
    const int gwarp = bid * 32 + wid;

    // ---------- phase 1: histogram (d_cnt is zero at entry) ----------
    for (int e4 = gtid; e4 < NE / 4; e4 += NTHREADS) {
        int4 r4 = *(const int4*)(rows + e4 * 4);
        atomicAdd(&d_cnt[r4.x], 1);
        atomicAdd(&d_cnt[r4.y], 1);
        atomicAdd(&d_cnt[r4.z], 1);
        atomicAdd(&d_cnt[r4.w], 1);
    }
    gridbar();

    // ---------- scan A (+ zero zsum for this run) ----------
    {
        int* s = (int*)sm;
        int i = bid * CHUNK + tid;
        int v = (tid < CHUNK && i < NN) ? d_cnt[i] : 0;
        s[tid] = v;
        __syncthreads();
        #pragma unroll
        for (int off = 1; off < 1024; off <<= 1) {
            int a = (tid >= off) ? s[tid - off] : 0;
            __syncthreads();
            s[tid] += a;
            __syncthreads();
        }
        if (tid < CHUNK && i < NN) d_rowptr[i] = s[tid] - v;
        if (tid == 0) d_btot[bid] = s[1023];
    }
    if (gtid < D) d_zsum[gtid] = 0.f;
    gridbar();

    // ---------- scan B (block 0) || colsum + feats->bf16 (blocks 1..147) ----------
    if (bid == 0) {
        int* s = (int*)sm;
        int v = (tid < NB) ? d_btot[tid] : 0;
        s[tid] = v;
        __syncthreads();
        #pragma unroll
        for (int off = 1; off < 1024; off <<= 1) {
            int a = (tid >= off) ? s[tid - off] : 0;
            __syncthreads();
            s[tid] += a;
            __syncthreads();
        }
        if (tid < NB) d_boff[tid] = s[tid] - v;
        if (tid == 0) d_rowptr[NN] = s[1023];
    } else {
        if (tid < D) scol[tid] = 0.f;
        __syncthreads();
        float4 cacc = make_float4(0.f, 0.f, 0.f, 0.f);
        int cwarp = (bid - 1) * 32 + wid;
        for (int r = cwarp; r < NN; r += 147 * 32) {
            float4 v = *(const float4*)(feats + (size_t)r * D + lane * 4);
            cacc.x += v.x; cacc.y += v.y; cacc.z += v.z; cacc.w += v.w;
            __nv_bfloat162* dst = (__nv_bfloat162*)(d_hb + (size_t)r * D + lane * 4);
            dst[0] = __floats2bfloat162_rn(v.x, v.y);
            dst[1] = __floats2bfloat162_rn(v.z, v.w);
        }
        atomicAdd(&scol[lane * 4 + 0], cacc.x);
        atomicAdd(&scol[lane * 4 + 1], cacc.y);
        atomicAdd(&scol[lane * 4 + 2], cacc.z);
        atomicAdd(&scol[lane * 4 + 3], cacc.w);
        __syncthreads();
        if (tid < D) atomicAdd(&d_zsum[tid], scol[tid]);
    }
    gridbar();

    // ---------- scan C: finalize rowptr/cursor; re-zero d_cnt for next replay ----------
    {
        int off = d_boff[bid];
        int i = bid * CHUNK + tid;
        if (tid < CHUNK && i < NN) {
            int val = d_rowptr[i] + off;
            d_rowptr[i] = val;
            d_cursor[i] = val;
        }
    }
    for (int i = gtid; i < NN; i += NTHREADS) d_cnt[i] = 0;
    gridbar();

    // ---------- scatter (packed edges) ----------
    for (int e4 = gtid; e4 < NE / 4; e4 += NTHREADS) {
        int4   r4 = *(const int4*)(rows + e4 * 4);
        int4   c4 = *(const int4*)(cols + e4 * 4);
        float4 v4 = *(const float4*)(vals + e4 * 4);
        int p;
        p = atomicAdd(&d_cursor[r4.x], 1); d_edge[p] = make_uint2((unsigned)c4.x, __float_as_uint(v4.x));
        p = atomicAdd(&d_cursor[r4.y], 1); d_edge[p] = make_uint2((unsigned)c4.y, __float_as_uint(v4.y));
        p = atomicAdd(&d_cursor[r4.z], 1); d_edge[p] = make_uint2((unsigned)c4.z, __float_as_uint(v4.z));
        p = atomicAdd(&d_cursor[r4.w], 1); d_edge[p] = make_uint2((unsigned)c4.w, __float_as_uint(v4.w));
    }
    gridbar();

    // ---------- GNN layers: fused SpMM(tile->smem) + tensor-core GEMM ----------
    const unsigned sA_base = (unsigned)__cvta_generic_to_shared(sA);
    const unsigned sB_base = (unsigned)__cvta_generic_to_shared(sB);
    const int wm = wid >> 2, wn = wid & 3;

    for (int l = 0; l < LAY; l++) {
        // W_l -> sB (bf16), block-local
        #pragma unroll
        for (int t = 0; t < 4; t++) {
            int j = tid + t * 1024;          // 4096 groups of 4 floats
            int row = j >> 5, seg = j & 31;
            float4 v = *(const float4*)(gW + (size_t)l * D * D + row * D + seg * 4);
            __nv_bfloat162* dst = (__nv_bfloat162*)(sB + row * SPITCH + seg * 4);
            dst[0] = __floats2bfloat162_rn(v.x, v.y);
            dst[1] = __floats2bfloat162_rn(v.z, v.w);
        }
        if (tid < D) scol[tid] = 0.f;
        // per-thread bias registers (fixed mapping across tiles)
        float bias[4][2];
        #pragma unroll
        for (int f = 0; f < 4; f++) {
            int nb = wn * 32 + f * 8 + (lane & 3) * 2;
            bias[f][0] = gb[l * D + nb];
            bias[f][1] = gb[l * D + nb + 1];
        }
        __syncthreads();

        for (int tile = bid; tile < NTILES; tile += NB) {
            int rb = tile * 128;

            // --- SpMM: 4 rows per warp, gather bf16 h, write bf16 into sA ---
            #pragma unroll
            for (int rr = 0; rr < 4; rr++) {
                int lr = wid + rr * 32;
                int row = rb + lr;
                float4 acc = make_float4(0.f, 0.f, 0.f, 0.f);
                if (row < NN) {
                    int e0 = d_rowptr[row], e1 = d_rowptr[row + 1];
                    for (int e = e0; e < e1; e += 32) {
                        int idx = e + lane;
                        uint2 ev = make_uint2(0u, 0u);
                        if (idx < e1) ev = d_edge[idx];
                        int nb2 = e1 - e; if (nb2 > 32) nb2 = 32;
                        for (int jb = 0; jb < nb2; jb += 8) {
                            uint2 hv[8]; float vv[8];
                            #pragma unroll
                            for (int u = 0; u < 8; u++) {
                                int c       = __shfl_sync(0xffffffffu, (int)ev.x, jb + u);
                                unsigned vb = __shfl_sync(0xffffffffu, ev.y, jb + u);
                                vv[u] = __uint_as_float(vb);
                                hv[u] = *(const uint2*)(d_hb + (size_t)c * D + lane * 4);
                            }
                            #pragma unroll
                            for (int u = 0; u < 8; u++) {
                                float2 f0 = __bfloat1622float2(*(const __nv_bfloat162*)&hv[u].x);
                                float2 f1 = __bfloat1622float2(*(const __nv_bfloat162*)&hv[u].y);
                                acc.x += vv[u] * f0.x; acc.y += vv[u] * f0.y;
                                acc.z += vv[u] * f1.x; acc.w += vv[u] * f1.y;
                            }
                        }
                    }
                }
                __nv_bfloat162* dst = (__nv_bfloat162*)(sA + lr * SPITCH + lane * 4);
                dst[0] = __floats2bfloat162_rn(acc.x, acc.y);
                dst[1] = __floats2bfloat162_rn(acc.z, acc.w);
            }
            __syncthreads();   // sA complete

            // --- GEMM on tile ---
            float c[4][4];
            #pragma unroll
            for (int f = 0; f < 4; f++)
                #pragma unroll
                for (int q = 0; q < 4; q++) c[f][q] = 0.f;

            #pragma unroll
            for (int ks = 0; ks < 8; ks++) {
                int k0 = ks * 16;
                unsigned a[4];
                unsigned aaddr = sA_base +
                    ((wm * 16 + (lane & 15)) * SPITCH + k0 + (lane >> 4) * 8) * 2;
                ldm_x4(a, aaddr);
                #pragma unroll
                for (int half = 0; half < 2; half++) {
                    int nbase = wn * 32 + half * 16;
                    int grp = lane >> 3;
                    int nrow = nbase + ((grp & 2) << 2) + (lane & 7);
                    int koff = k0 + ((grp & 1) << 3);
                    unsigned b[4];
                    unsigned baddr = sB_base + (nrow * SPITCH + koff) * 2;
                    ldm_x4(b, baddr);
                    mma_bf16(c[half * 2 + 0], a, b[0], b[1]);
                    mma_bf16(c[half * 2 + 1], a, b[2], b[3]);
                }
            }
            __syncthreads();   // done reading sA (next tile may overwrite)

            // --- epilogue: bias + ELU -> bf16 h, column sums ---
            int r0g = rb + wm * 16 + (lane >> 2);
            int r1g = r0g + 8;
            bool v0 = r0g < NN, v1 = r1g < NN;
            #pragma unroll
            for (int f = 0; f < 4; f++) {
                int nb = wn * 32 + f * 8 + (lane & 3) * 2;
                float o0 = eluf(c[f][0] + bias[f][0]), o1 = eluf(c[f][1] + bias[f][1]);
                float o2 = eluf(c[f][2] + bias[f][0]), o3 = eluf(c[f][3] + bias[f][1]);
                if (v0) *(__nv_bfloat162*)(d_hb + (size_t)r0g * D + nb) =
                            __floats2bfloat162_rn(o0, o1);
                if (v1) *(__nv_bfloat162*)(d_hb + (size_t)r1g * D + nb) =
                            __floats2bfloat162_rn(o2, o3);
                float s0 = (v0 ? o0 : 0.f) + (v1 ? o2 : 0.f);
                float s1 = (v0 ? o1 : 0.f) + (v1 ? o3 : 0.f);
                #pragma unroll
                for (int off = 4; off < 32; off <<= 1) {
                    s0 += __shfl_xor_sync(0xffffffffu, s0, off);
                    s1 += __shfl_xor_sync(0xffffffffu, s1, off);
                }
                if (lane < 4) {
                    atomicAdd(&scol[nb], s0);
                    atomicAdd(&scol[nb + 1], s1);
                }
            }
        }
        __syncthreads();
        if (tid < D) atomicAdd(&d_zsum[tid], scol[tid]);
        gridbar();
    }

    // ---------- tail ----------
    float* s_hz   = sm;
    float* s_wcol = sm + 128;
    {
        const float inv = 1.0f / ((float)(LAY + 1) * (float)NN);
        float4 z4 = *(const float4*)(d_zsum + lane * 4);
        z4.x *= inv; z4.y *= inv; z4.z *= inv; z4.w *= inv;
        for (int o = wid; o < D; o += 32) {
            float4 w = *(const float4*)(fc1W + (size_t)o * D + lane * 4);
            float p = z4.x * w.x + z4.y * w.y + z4.z * w.z + z4.w * w.w;
            #pragma unroll
            for (int off = 16; off > 0; off >>= 1) p += __shfl_xor_sync(0xffffffffu, p, off);
            if (lane == 0) {
                float s = p + fc1b[o];
                s_hz[o] = s > 0.f ? s : 0.2f * s;
            }
        }
        __syncthreads();
    }
    {
        float4 hz4 = *(const float4*)(s_hz + lane * 4);
        for (int j = wid; j < RK * D; j += 32) {
            float4 w = *(const float4*)(fcW + (size_t)j * D + lane * 4);
            float p = hz4.x * w.x + hz4.y * w.y + hz4.z * w.z + hz4.w * w.w;
            #pragma unroll
            for (int off = 16; off > 0; off >>= 1) p += __shfl_xor_sync(0xffffffffu, p, off);
            if (lane == 0) s_wcol[j] = p + fcb[j];
        }
        __syncthreads();
    }
    {
        float4 hz4 = *(const float4*)(s_hz + lane * 4);
        for (int node = gwarp; node < NN; node += NWARPS) {
            const float* wb = frW + (size_t)node * RK * D;
            float4 wu = make_float4(0.f, 0.f, 0.f, 0.f);
            #pragma unroll
            for (int r = 0; r < RK; r++) {
                float4 w = *(const float4*)(wb + r * D + lane * 4);
                float p = hz4.x * w.x + hz4.y * w.y + hz4.z * w.z + hz4.w * w.w;
                #pragma unroll
                for (int off = 16; off > 0; off >>= 1) p += __shfl_xor_sync(0xffffffffu, p, off);
                float wr = p + frb[(size_t)node * RK + r];
                float4 wc = *(const float4*)(s_wcol + r * D + lane * 4);
                wu.x += wr * wc.x; wu.y += wr * wc.y;
                wu.z += wr * wc.z; wu.w += wr * wc.w;
            }
            float4 iv = *(const float4*)(ini + (size_t)node * D + lane * 4);
            float4 ov;
            ov.x = iv.x + wu.x * iv.x; ov.y = iv.y + wu.y * iv.y;
            ov.z = iv.z + wu.z * iv.z; ov.w = iv.w + wu.w * iv.w;
            *(float4*)(out + (size_t)node * D + lane * 4) = ov;
        }
    }
}

// ---------------- launch ----------------
extern "C" void kernel_launch(void* const* d_in, const int* in_sizes, int n_in,
                              void* d_out, int out_size) {
    const int*   rows  = (const int*)d_in[0];
    const int*   cols  = (const int*)d_in[1];
    const float* vals  = (const float*)d_in[2];
    const float* feats = (const float*)d_in[3];
    const float* gW    = (const float*)d_in[4];
    const float* gb    = (const float*)d_in[5];
    const float* fc1W  = (const float*)d_in[6];
    const float* fc1b  = (const float*)d_in[7];
    const float* frW   = (const float*)d_in[8];
    const float* frb   = (const float*)d_in[9];
    const float* fcW   = (const float*)d_in[10];
    const float* fcb   = (const float*)d_in[11];
    const float* ini   = (const float*)d_in[12];
    float* out = (float*)d_out;

    cudaFuncSetAttribute(k_all, cudaFuncAttributeMaxDynamicSharedMemorySize, SMEM_BYTES);
    k_all<<<NB, 1024, SMEM_BYTES>>>(rows, cols, vals, feats, gW, gb,
                                    fc1W, fc1b, frW, frb, fcW, fcb, ini, out);
}